// round 3
// baseline (speedup 1.0000x reference)
#include <cuda_runtime.h>
#include <stdint.h>

// Problem constants (fixed by the dataset)
#define BATCH   1024
#define IN_DIM  1024
#define OUT_DIM 40960
#define FANIN   7

// Tiling
#define BTILE      32
#define XS_STRIDE  1025           // floats; 1025 % 32 == 1 -> conflict-free gather
#define THREADS    512
#define WARPS      16
#define GRID_B     (BATCH / BTILE)            // 32
#define GRID_O     32
#define O_BLOCK    (OUT_DIM / GRID_O)         // 1280
#define O_PER_WARP (O_BLOCK / WARPS)          // 80
#define SMEM_BYTES (BTILE * XS_STRIDE * 4)    // 131200 B

// Packed per-output metadata: 48B = uint4 (7x u16 idx*4) + 7 f32 vals + pad
// 40960 * 48B = 1.97 MB device scratch (allowed: __device__ global)
__device__ __align__(16) uint4 g_meta[OUT_DIM * 3];

__global__ void prep_kernel(const int* __restrict__ idx,
                            const float* __restrict__ vals) {
    int o = blockIdx.x * blockDim.x + threadIdx.x;
    if (o >= OUT_DIM) return;
    unsigned id[FANIN];
    float v[FANIN];
#pragma unroll
    for (int k = 0; k < FANIN; k++) {
        id[k] = (unsigned)idx[o * FANIN + k] * 4u;   // pre-scale to byte offset
        v[k]  = vals[o * FANIN + k];
    }
    uint4 mi, ma, mb;
    mi.x = id[0] | (id[1] << 16);
    mi.y = id[2] | (id[3] << 16);
    mi.z = id[4] | (id[5] << 16);
    mi.w = id[6];
    ma.x = __float_as_uint(v[0]); ma.y = __float_as_uint(v[1]);
    ma.z = __float_as_uint(v[2]); ma.w = __float_as_uint(v[3]);
    mb.x = __float_as_uint(v[4]); mb.y = __float_as_uint(v[5]);
    mb.z = __float_as_uint(v[6]); mb.w = 0u;
    uint4* dst = g_meta + (size_t)o * 3;
    dst[0] = mi; dst[1] = ma; dst[2] = mb;
}

// Dot product of 7 gathered x values with 7 vals. xb is this lane's smem row
// base (byte pointer). Gathers are conflict-free: bank = (lane + idx) % 32.
__device__ __forceinline__ float dot7(const char* xb, uint4 mi, uint4 ma, uint4 mb) {
    float g0 = *reinterpret_cast<const float*>(xb + (mi.x & 0xFFFFu));
    float g1 = *reinterpret_cast<const float*>(xb + (mi.x >> 16));
    float g2 = *reinterpret_cast<const float*>(xb + (mi.y & 0xFFFFu));
    float g3 = *reinterpret_cast<const float*>(xb + (mi.y >> 16));
    float g4 = *reinterpret_cast<const float*>(xb + (mi.z & 0xFFFFu));
    float g5 = *reinterpret_cast<const float*>(xb + (mi.z >> 16));
    float g6 = *reinterpret_cast<const float*>(xb + (mi.w & 0xFFFFu));
    float s0 = fmaf(__uint_as_float(ma.x), g0, __uint_as_float(ma.y) * g1);
    float s1 = fmaf(__uint_as_float(ma.z), g2, __uint_as_float(ma.w) * g3);
    float s2 = fmaf(__uint_as_float(mb.x), g4, __uint_as_float(mb.y) * g5);
    float s3 = __uint_as_float(mb.z) * g6;
    return (s0 + s1) + (s2 + s3);
}

extern __shared__ float xs[];   // [BTILE][XS_STRIDE]

__global__ __launch_bounds__(THREADS, 1)
void mb_proj_kernel(const float* __restrict__ x, float* __restrict__ y) {
    const int b0 = blockIdx.y * BTILE;

    // ---- Fill smem x tile: 32 rows x 1024 floats, stride 1025 -------------
    // Warp mapping: 4 rows x 8 float4-chunks -> LDG 4x128B segments,
    // STS banks = (r + 4c + j) mod 32 with (dr + 4*dc) covering 0..31 ->
    // conflict-free scalar stores.
    {
        const float4* xg = reinterpret_cast<const float4*>(x + (size_t)b0 * IN_DIM);
        for (int t = threadIdx.x; t < BTILE * (IN_DIM / 4); t += THREADS) {
            int lane5 = t & 31;
            int blk   = t >> 5;
            int r = ((blk >> 5) << 2) + (lane5 >> 3);   // 0..31
            int c = ((blk & 31) << 3) + (lane5 & 7);    // 0..255 (float4 units)
            float4 v = xg[r * (IN_DIM / 4) + c];
            float* d = xs + r * XS_STRIDE + (c << 2);
            d[0] = v.x; d[1] = v.y; d[2] = v.z; d[3] = v.w;
        }
    }
    __syncthreads();

    const int warp = threadIdx.x >> 5;
    const int lane = threadIdx.x & 31;

    // Lane = batch row within the tile; o is uniform across the warp.
    const char* xb = reinterpret_cast<const char*>(xs) + lane * (XS_STRIDE * 4);
    float* yrow = y + (size_t)(b0 + lane) * OUT_DIM;
    const int o_start = blockIdx.x * O_BLOCK + warp * O_PER_WARP;

    // 20 groups of 4 outputs; 12 independent uniform LDG.128 per group (MLP),
    // then 28 conflict-free LDS gathers, one 16B sector-aligned STG.128.
#pragma unroll 4
    for (int og = 0; og < O_PER_WARP; og += 4) {
        const int o = o_start + og;
        const uint4* mp = g_meta + (size_t)o * 3;
        uint4 m0i = mp[0],  m0a = mp[1],  m0b = mp[2];
        uint4 m1i = mp[3],  m1a = mp[4],  m1b = mp[5];
        uint4 m2i = mp[6],  m2a = mp[7],  m2b = mp[8];
        uint4 m3i = mp[9],  m3a = mp[10], m3b = mp[11];

        float4 out;
        out.x = dot7(xb, m0i, m0a, m0b);
        out.y = dot7(xb, m1i, m1a, m1b);
        out.z = dot7(xb, m2i, m2a, m2b);
        out.w = dot7(xb, m3i, m3a, m3b);
        *reinterpret_cast<float4*>(yrow + o) = out;
    }
}

extern "C" void kernel_launch(void* const* d_in, const int* in_sizes, int n_in,
                              void* d_out, int out_size) {
    const float* x    = (const float*)d_in[0];   // [1024, 1024] f32
    const float* vals = (const float*)d_in[1];   // [40960, 7]   f32
    const int*   idx  = (const int*)d_in[2];     // [40960, 7]   i32
    float*       y    = (float*)d_out;           // [1024, 40960] f32

    (void)in_sizes; (void)n_in; (void)out_size;

    cudaFuncSetAttribute(mb_proj_kernel,
                         cudaFuncAttributeMaxDynamicSharedMemorySize, SMEM_BYTES);

    prep_kernel<<<(OUT_DIM + 255) / 256, 256>>>(idx, vals);

    dim3 grid(GRID_O, GRID_B);
    mb_proj_kernel<<<grid, THREADS, SMEM_BYTES>>>(x, y);
}

// round 4
// speedup vs baseline: 1.0886x; 1.0886x over previous
#include <cuda_runtime.h>
#include <stdint.h>

// Problem constants (fixed by the dataset)
#define BATCH   1024
#define IN_DIM  1024
#define OUT_DIM 40960
#define FANIN   7

// Tiling
#define BTILE      32
#define XS_STRIDE  1025           // floats; 1025 % 32 == 1 -> conflict-free gather
#define THREADS    1024
#define WARPS      32
#define GRID_B     (BATCH / BTILE)            // 32
#define GRID_O     32
#define O_BLOCK    (OUT_DIM / GRID_O)         // 1280
#define O_PER_WARP (O_BLOCK / WARPS)          // 40
#define SMEM_BYTES (BTILE * XS_STRIDE * 4)    // 131200 B

// Packed per-output metadata: 48B = uint4 (7x u16 idx*4) + 7 f32 vals + pad
__device__ __align__(16) uint4 g_meta[OUT_DIM * 3];

__global__ void prep_kernel(const int* __restrict__ idx,
                            const float* __restrict__ vals) {
    int o = blockIdx.x * blockDim.x + threadIdx.x;
    if (o >= OUT_DIM) return;
    unsigned id[FANIN];
    float v[FANIN];
#pragma unroll
    for (int k = 0; k < FANIN; k++) {
        id[k] = (unsigned)idx[o * FANIN + k] * 4u;   // pre-scale to byte offset
        v[k]  = vals[o * FANIN + k];
    }
    uint4 mi, ma, mb;
    mi.x = id[0] | (id[1] << 16);
    mi.y = id[2] | (id[3] << 16);
    mi.z = id[4] | (id[5] << 16);
    mi.w = id[6];
    ma.x = __float_as_uint(v[0]); ma.y = __float_as_uint(v[1]);
    ma.z = __float_as_uint(v[2]); ma.w = __float_as_uint(v[3]);
    mb.x = __float_as_uint(v[4]); mb.y = __float_as_uint(v[5]);
    mb.z = __float_as_uint(v[6]); mb.w = 0u;
    uint4* dst = g_meta + (size_t)o * 3;
    dst[0] = mi; dst[1] = ma; dst[2] = mb;
}

// Dot product of 7 gathered x values with 7 vals. xb is this lane's smem row
// base (byte pointer). Gathers are conflict-free: bank = (lane + idx) % 32.
__device__ __forceinline__ float dot7(const char* xb, uint4 mi, uint4 ma, uint4 mb) {
    float g0 = *reinterpret_cast<const float*>(xb + (mi.x & 0xFFFFu));
    float g1 = *reinterpret_cast<const float*>(xb + (mi.x >> 16));
    float g2 = *reinterpret_cast<const float*>(xb + (mi.y & 0xFFFFu));
    float g3 = *reinterpret_cast<const float*>(xb + (mi.y >> 16));
    float g4 = *reinterpret_cast<const float*>(xb + (mi.z & 0xFFFFu));
    float g5 = *reinterpret_cast<const float*>(xb + (mi.z >> 16));
    float g6 = *reinterpret_cast<const float*>(xb + (mi.w & 0xFFFFu));
    float s0 = fmaf(__uint_as_float(ma.x), g0, __uint_as_float(ma.y) * g1);
    float s1 = fmaf(__uint_as_float(ma.z), g2, __uint_as_float(ma.w) * g3);
    float s2 = fmaf(__uint_as_float(mb.x), g4, __uint_as_float(mb.y) * g5);
    float s3 = __uint_as_float(mb.z) * g6;
    return (s0 + s1) + (s2 + s3);
}

extern __shared__ float xs[];   // [BTILE][XS_STRIDE]

__global__ __launch_bounds__(THREADS, 1)
void mb_proj_kernel(const float* __restrict__ x, float* __restrict__ y) {
    const int b0 = blockIdx.y * BTILE;

    // ---- Fill smem x tile: 32 rows x 1024 floats, stride 1025 -------------
    // Warp mapping: 4 rows x 8 float4-chunks -> coalesced LDG segments,
    // STS banks = (r + 4c + j) mod 32 cover all 32 -> conflict-free stores.
    {
        const float4* xg = reinterpret_cast<const float4*>(x + (size_t)b0 * IN_DIM);
        for (int t = threadIdx.x; t < BTILE * (IN_DIM / 4); t += THREADS) {
            int lane5 = t & 31;
            int blk   = t >> 5;
            int r = ((blk >> 5) << 2) + (lane5 >> 3);   // 0..31
            int c = ((blk & 31) << 3) + (lane5 & 7);    // 0..255 (float4 units)
            float4 v = xg[r * (IN_DIM / 4) + c];
            float* d = xs + r * XS_STRIDE + (c << 2);
            d[0] = v.x; d[1] = v.y; d[2] = v.z; d[3] = v.w;
        }
    }
    __syncthreads();

    const int warp = threadIdx.x >> 5;
    const int lane = threadIdx.x & 31;

    // Lane = batch row within the tile; o is uniform across the warp.
    const char* xb = reinterpret_cast<const char*>(xs) + lane * (XS_STRIDE * 4);
    float* yrow = y + (size_t)(b0 + lane) * OUT_DIM;
    const int o_start = blockIdx.x * O_BLOCK + warp * O_PER_WARP;

    // 10 groups of 4 outputs, metadata loaded in two halves of 6 x LDG.128
    // to keep live registers <= 64 at 1024 threads (no spills).
    // Gathers: 28 conflict-free LDS per group; store: one 16B-aligned STG.128.
#pragma unroll 2
    for (int og = 0; og < O_PER_WARP; og += 4) {
        const int o = o_start + og;
        const uint4* mp = g_meta + (size_t)o * 3;

        float4 out;
        {
            uint4 m0i = mp[0], m0a = mp[1], m0b = mp[2];
            uint4 m1i = mp[3], m1a = mp[4], m1b = mp[5];
            out.x = dot7(xb, m0i, m0a, m0b);
            out.y = dot7(xb, m1i, m1a, m1b);
        }
        {
            uint4 m2i = mp[6], m2a = mp[7],  m2b = mp[8];
            uint4 m3i = mp[9], m3a = mp[10], m3b = mp[11];
            out.z = dot7(xb, m2i, m2a, m2b);
            out.w = dot7(xb, m3i, m3a, m3b);
        }
        *reinterpret_cast<float4*>(yrow + o) = out;
    }
}

extern "C" void kernel_launch(void* const* d_in, const int* in_sizes, int n_in,
                              void* d_out, int out_size) {
    const float* x    = (const float*)d_in[0];   // [1024, 1024] f32
    const float* vals = (const float*)d_in[1];   // [40960, 7]   f32
    const int*   idx  = (const int*)d_in[2];     // [40960, 7]   i32
    float*       y    = (float*)d_out;           // [1024, 40960] f32

    (void)in_sizes; (void)n_in; (void)out_size;

    cudaFuncSetAttribute(mb_proj_kernel,
                         cudaFuncAttributeMaxDynamicSharedMemorySize, SMEM_BYTES);

    prep_kernel<<<(OUT_DIM + 255) / 256, 256>>>(idx, vals);

    dim3 grid(GRID_O, GRID_B);
    mb_proj_kernel<<<grid, THREADS, SMEM_BYTES>>>(x, y);
}

// round 6
// speedup vs baseline: 1.2599x; 1.1574x over previous
#include <cuda_runtime.h>
#include <stdint.h>

// Problem constants (fixed by the dataset)
#define BATCH   1024
#define IN_DIM  1024
#define OUT_DIM 40960
#define FANIN   7

// Tiling
#define BTILE      32
#define XS_STRIDE  1025           // floats; 1025 % 32 == 1 -> conflict-free gather
#define THREADS    1024
#define WARPS      32
#define GRID_B     (BATCH / BTILE)            // 32
#define GRID_O     40
#define O_BLOCK    (OUT_DIM / GRID_O)         // 1024
#define O_PER_WARP (O_BLOCK / WARPS)          // 32

#define XS_FLOATS    (BTILE * XS_STRIDE)      // 32800
#define STG_STRIDE   33                       // 33 % 32 == 1 -> conflict-free
#define STG_PER_WARP (16 * STG_STRIDE)        // 528 floats per warp
#define SMEM_FLOATS  (XS_FLOATS + WARPS * STG_PER_WARP)
#define SMEM_BYTES   (SMEM_FLOATS * 4)        // 131200 + 67584 = 198784 B

// Packed per-output metadata: 48B = uint4 (7x u16 idx*4) + 7 f32 vals + pad
__device__ __align__(16) uint4 g_meta[OUT_DIM * 3];

__global__ void prep_kernel(const int* __restrict__ idx,
                            const float* __restrict__ vals) {
    int o = blockIdx.x * blockDim.x + threadIdx.x;
    if (o >= OUT_DIM) return;
    unsigned id[FANIN];
    float v[FANIN];
#pragma unroll
    for (int k = 0; k < FANIN; k++) {
        id[k] = (unsigned)idx[o * FANIN + k] * 4u;   // pre-scale to byte offset
        v[k]  = vals[o * FANIN + k];
    }
    uint4 mi, ma, mb;
    mi.x = id[0] | (id[1] << 16);
    mi.y = id[2] | (id[3] << 16);
    mi.z = id[4] | (id[5] << 16);
    mi.w = id[6];
    ma.x = __float_as_uint(v[0]); ma.y = __float_as_uint(v[1]);
    ma.z = __float_as_uint(v[2]); ma.w = __float_as_uint(v[3]);
    mb.x = __float_as_uint(v[4]); mb.y = __float_as_uint(v[5]);
    mb.z = __float_as_uint(v[6]); mb.w = 0u;
    uint4* dst = g_meta + (size_t)o * 3;
    dst[0] = mi; dst[1] = ma; dst[2] = mb;
}

// Dot product of 7 gathered x values with 7 vals. xb is this lane's smem row
// base (byte pointer). Gathers are conflict-free: bank = (lane + idx) % 32.
__device__ __forceinline__ float dot7(const char* xb, uint4 mi, uint4 ma, uint4 mb) {
    float g0 = *reinterpret_cast<const float*>(xb + (mi.x & 0xFFFFu));
    float g1 = *reinterpret_cast<const float*>(xb + (mi.x >> 16));
    float g2 = *reinterpret_cast<const float*>(xb + (mi.y & 0xFFFFu));
    float g3 = *reinterpret_cast<const float*>(xb + (mi.y >> 16));
    float g4 = *reinterpret_cast<const float*>(xb + (mi.z & 0xFFFFu));
    float g5 = *reinterpret_cast<const float*>(xb + (mi.z >> 16));
    float g6 = *reinterpret_cast<const float*>(xb + (mi.w & 0xFFFFu));
    float s0 = fmaf(__uint_as_float(ma.x), g0, __uint_as_float(ma.y) * g1);
    float s1 = fmaf(__uint_as_float(ma.z), g2, __uint_as_float(ma.w) * g3);
    float s2 = fmaf(__uint_as_float(mb.x), g4, __uint_as_float(mb.y) * g5);
    float s3 = __uint_as_float(mb.z) * g6;
    return (s0 + s1) + (s2 + s3);
}

extern __shared__ float smem_all[];   // [XS_FLOATS] x-tile | [WARPS][528] staging

__global__ __launch_bounds__(THREADS, 1)
void mb_proj_kernel(const float* __restrict__ x, float* __restrict__ y) {
    float* xs = smem_all;
    const int b0 = blockIdx.y * BTILE;

    // ---- Fill smem x tile: 32 rows x 1024 floats, stride 1025 -------------
    // Warp mapping: 4 rows x 8 float4-chunks -> coalesced LDG segments,
    // STS banks = (r + 4c + j) mod 32 cover all 32 -> conflict-free stores.
    {
        const float4* xg = reinterpret_cast<const float4*>(x + (size_t)b0 * IN_DIM);
        for (int t = threadIdx.x; t < BTILE * (IN_DIM / 4); t += THREADS) {
            int lane5 = t & 31;
            int blk   = t >> 5;
            int r = ((blk >> 5) << 2) + (lane5 >> 3);   // 0..31
            int c = ((blk & 31) << 3) + (lane5 & 7);    // 0..255 (float4 units)
            float4 v = xg[r * (IN_DIM / 4) + c];
            float* d = xs + r * XS_STRIDE + (c << 2);
            d[0] = v.x; d[1] = v.y; d[2] = v.z; d[3] = v.w;
        }
    }
    __syncthreads();

    const int warp = threadIdx.x >> 5;
    const int lane = threadIdx.x & 31;

    // Compute mapping: lane = batch row, o uniform across warp.
    const char* xb = reinterpret_cast<const char*>(xs) + lane * (XS_STRIDE * 4);
    float* stg = smem_all + XS_FLOATS + warp * STG_PER_WARP;

    const int o_base = blockIdx.x * O_BLOCK + warp * O_PER_WARP;

    // Store-phase mapping: lane = (hh, t): o = o0 + t, b = i + 16*hh.
    const int t  = lane & 15;
    const int hh = lane >> 4;

#pragma unroll
    for (int half = 0; half < 2; half++) {
        const int o0 = o_base + half * 16;
        const uint4* mp = g_meta + (size_t)o0 * 3;

        // ---- Compute 16 outputs into staging, software-pipelined meta ----
        uint4 c0 = mp[0], c1 = mp[1], c2 = mp[2];
#pragma unroll
        for (int s = 0; s < 16; s++) {
            uint4 n0, n1, n2;
            if (s < 15) {
                const uint4* np = mp + 3 * (s + 1);
                n0 = np[0]; n1 = np[1]; n2 = np[2];
            } else {
                n0 = c0; n1 = c1; n2 = c2;
            }
            // STS bank = (s + lane) % 32 -> conflict-free
            stg[s * STG_STRIDE + lane] = dot7(xb, c0, c1, c2);
            c0 = n0; c1 = n1; c2 = n2;
        }
        __syncwarp();

        // ---- Transposed store: coalesced y rows -------------------------
        // LDS addr = t*33 + 16*hh + i -> bank = (t + 16*hh + i) % 32, all
        // 32 distinct -> conflict-free. STG: 2 row-segments of 64B per iter.
        {
            const float* sp = stg + t * STG_STRIDE + 16 * hh;
            float* yp = y + (size_t)(b0 + 16 * hh) * OUT_DIM + o0 + t;
#pragma unroll
            for (int i = 0; i < 16; i++) {
                yp[(size_t)i * OUT_DIM] = sp[i];
            }
        }
        __syncwarp();
    }
}

extern "C" void kernel_launch(void* const* d_in, const int* in_sizes, int n_in,
                              void* d_out, int out_size) {
    const float* x    = (const float*)d_in[0];   // [1024, 1024] f32
    const float* vals = (const float*)d_in[1];   // [40960, 7]   f32
    const int*   idx  = (const int*)d_in[2];     // [40960, 7]   i32
    float*       y    = (float*)d_out;           // [1024, 40960] f32

    (void)in_sizes; (void)n_in; (void)out_size;

    cudaFuncSetAttribute(mb_proj_kernel,
                         cudaFuncAttributeMaxDynamicSharedMemorySize, SMEM_BYTES);

    prep_kernel<<<(OUT_DIM + 255) / 256, 256>>>(idx, vals);

    dim3 grid(GRID_O, GRID_B);
    mb_proj_kernel<<<grid, THREADS, SMEM_BYTES>>>(x, y);
}